// round 1
// baseline (speedup 1.0000x reference)
#include <cuda_runtime.h>
#include <cstdint>

#define S_LEN   2048
#define HEADS   16
#define DH      64
#define BM      64
#define BN      64
#define LDK     68          // padded stride (floats) for shared tiles
#define NTHREADS 128

__device__ __forceinline__ unsigned f2tf32(float f) {
    unsigned r;
    asm("cvt.rna.tf32.f32 %0, %1;" : "=r"(r) : "f"(f));
    return r;
}

__device__ __forceinline__ void mma_tf32(float c[4], const unsigned a[4],
                                         unsigned b0, unsigned b1) {
    asm volatile(
        "mma.sync.aligned.m16n8k8.row.col.f32.tf32.tf32.f32 "
        "{%0,%1,%2,%3}, {%4,%5,%6,%7}, {%8,%9}, {%0,%1,%2,%3};\n"
        : "+f"(c[0]), "+f"(c[1]), "+f"(c[2]), "+f"(c[3])
        : "r"(a[0]), "r"(a[1]), "r"(a[2]), "r"(a[3]), "r"(b0), "r"(b1));
}

__global__ __launch_bounds__(NTHREADS, 4)
void fa_tf32_kernel(const float* __restrict__ Q, const float* __restrict__ K,
                    const float* __restrict__ V, const float* __restrict__ mask,
                    float* __restrict__ out)
{
    __shared__ float Ksh[BN * LDK];   // K tile; reused as P staging after QK^T
    __shared__ float Vsh[BN * LDK];
    __shared__ float msh[BN];

    const int tid  = threadIdx.x;
    const int warp = tid >> 5;
    const int lane = tid & 31;
    const int gid  = lane >> 2;   // row group 0..7
    const int tig  = lane & 3;    // thread-in-group 0..3

    const int bh = blockIdx.y;            // fused b*H + h
    const int b  = bh / HEADS;
    const int q0 = blockIdx.x * BM + warp * 16;

    const float* Qbase = Q + ((size_t)bh * S_LEN + q0) * DH;
    const float* Kbase = K + (size_t)bh * S_LEN * DH;
    const float* Vbase = V + (size_t)bh * S_LEN * DH;
    const float* mbase = mask + (size_t)b * S_LEN;

    // ---- Q fragments (tf32), pre-scaled by 1/sqrt(64) = 0.125 (exact) ----
    unsigned qa[8][4];
    #pragma unroll
    for (int kt = 0; kt < 8; kt++) {
        const int c0 = kt * 8 + tig;
        qa[kt][0] = f2tf32(Qbase[(size_t)gid       * DH + c0    ] * 0.125f);
        qa[kt][1] = f2tf32(Qbase[(size_t)(gid + 8) * DH + c0    ] * 0.125f);
        qa[kt][2] = f2tf32(Qbase[(size_t)gid       * DH + c0 + 4] * 0.125f);
        qa[kt][3] = f2tf32(Qbase[(size_t)(gid + 8) * DH + c0 + 4] * 0.125f);
    }

    float o[8][4];
    #pragma unroll
    for (int nt = 0; nt < 8; nt++)
        #pragma unroll
        for (int j = 0; j < 4; j++) o[nt][j] = 0.f;

    float m0 = -1e30f, m1 = -1e30f;   // running row maxima (rows gid, gid+8)
    float l0 = 0.f,   l1 = 0.f;       // running row sums

    for (int kv0 = 0; kv0 < S_LEN; kv0 += BN) {
        __syncthreads();   // prior iteration's PV reads of Ksh/Vsh complete

        // ---- cooperative load of K, V tiles (tf32-converted) + mask ----
        #pragma unroll
        for (int it = 0; it < 8; it++) {
            const int i  = tid + it * NTHREADS;      // 0..1023
            const int r  = i >> 4;
            const int c4 = (i & 15) << 2;
            const float4 k4 = *(const float4*)(Kbase + (size_t)(kv0 + r) * DH + c4);
            Ksh[r * LDK + c4 + 0] = __uint_as_float(f2tf32(k4.x));
            Ksh[r * LDK + c4 + 1] = __uint_as_float(f2tf32(k4.y));
            Ksh[r * LDK + c4 + 2] = __uint_as_float(f2tf32(k4.z));
            Ksh[r * LDK + c4 + 3] = __uint_as_float(f2tf32(k4.w));
            const float4 v4 = *(const float4*)(Vbase + (size_t)(kv0 + r) * DH + c4);
            Vsh[r * LDK + c4 + 0] = __uint_as_float(f2tf32(v4.x));
            Vsh[r * LDK + c4 + 1] = __uint_as_float(f2tf32(v4.y));
            Vsh[r * LDK + c4 + 2] = __uint_as_float(f2tf32(v4.z));
            Vsh[r * LDK + c4 + 3] = __uint_as_float(f2tf32(v4.w));
        }
        if (tid < BN) msh[tid] = -1000000.0f * (1.0f - mbase[kv0 + tid]);
        __syncthreads();

        // ---- S = Q K^T  (scaled already), 16x64 per warp ----
        float sacc[8][4];
        #pragma unroll
        for (int nt = 0; nt < 8; nt++) {
            #pragma unroll
            for (int j = 0; j < 4; j++) sacc[nt][j] = 0.f;
            #pragma unroll
            for (int kt = 0; kt < 8; kt++) {
                const float* kp = &Ksh[(nt * 8 + gid) * LDK + kt * 8 + tig];
                unsigned b0 = __float_as_uint(kp[0]);
                unsigned b1 = __float_as_uint(kp[4]);
                mma_tf32(sacc[nt], qa[kt], b0, b1);
            }
        }

        // ---- additive mask + online softmax ----
        float mx0 = -1e30f, mx1 = -1e30f;
        #pragma unroll
        for (int nt = 0; nt < 8; nt++) {
            const float add0 = msh[nt * 8 + 2 * tig];
            const float add1 = msh[nt * 8 + 2 * tig + 1];
            sacc[nt][0] += add0; sacc[nt][1] += add1;
            sacc[nt][2] += add0; sacc[nt][3] += add1;
            mx0 = fmaxf(mx0, fmaxf(sacc[nt][0], sacc[nt][1]));
            mx1 = fmaxf(mx1, fmaxf(sacc[nt][2], sacc[nt][3]));
        }
        mx0 = fmaxf(mx0, __shfl_xor_sync(0xffffffffu, mx0, 1));
        mx0 = fmaxf(mx0, __shfl_xor_sync(0xffffffffu, mx0, 2));
        mx1 = fmaxf(mx1, __shfl_xor_sync(0xffffffffu, mx1, 1));
        mx1 = fmaxf(mx1, __shfl_xor_sync(0xffffffffu, mx1, 2));

        const float nm0 = fmaxf(m0, mx0);
        const float nm1 = fmaxf(m1, mx1);
        const float al0 = __expf(m0 - nm0);
        const float al1 = __expf(m1 - nm1);

        float s0 = 0.f, s1 = 0.f;
        #pragma unroll
        for (int nt = 0; nt < 8; nt++) {
            float p0 = __expf(sacc[nt][0] - nm0);
            float p1 = __expf(sacc[nt][1] - nm0);
            float p2 = __expf(sacc[nt][2] - nm1);
            float p3 = __expf(sacc[nt][3] - nm1);
            s0 += p0 + p1;
            s1 += p2 + p3;
            sacc[nt][0] = p0; sacc[nt][1] = p1;
            sacc[nt][2] = p2; sacc[nt][3] = p3;
        }
        s0 += __shfl_xor_sync(0xffffffffu, s0, 1);
        s0 += __shfl_xor_sync(0xffffffffu, s0, 2);
        s1 += __shfl_xor_sync(0xffffffffu, s1, 1);
        s1 += __shfl_xor_sync(0xffffffffu, s1, 2);
        l0 = l0 * al0 + s0;
        l1 = l1 * al1 + s1;
        m0 = nm0; m1 = nm1;

        #pragma unroll
        for (int nt = 0; nt < 8; nt++) {
            o[nt][0] *= al0; o[nt][1] *= al0;
            o[nt][2] *= al1; o[nt][3] *= al1;
        }

        // ---- stage P (tf32) into this warp's 16 rows of Ksh (K is dead) ----
        __syncthreads();   // all warps finished reading K tile
        float* Pst = Ksh + warp * 16 * LDK;
        #pragma unroll
        for (int nt = 0; nt < 8; nt++) {
            const int c = nt * 8 + 2 * tig;
            Pst[gid * LDK + c    ]      = __uint_as_float(f2tf32(sacc[nt][0]));
            Pst[gid * LDK + c + 1]      = __uint_as_float(f2tf32(sacc[nt][1]));
            Pst[(gid + 8) * LDK + c    ] = __uint_as_float(f2tf32(sacc[nt][2]));
            Pst[(gid + 8) * LDK + c + 1] = __uint_as_float(f2tf32(sacc[nt][3]));
        }
        __syncwarp();

        // ---- O += P @ V ----
        #pragma unroll
        for (int kt = 0; kt < 8; kt++) {
            unsigned pa[4];
            pa[0] = __float_as_uint(Pst[gid       * LDK + kt * 8 + tig    ]);
            pa[1] = __float_as_uint(Pst[(gid + 8) * LDK + kt * 8 + tig    ]);
            pa[2] = __float_as_uint(Pst[gid       * LDK + kt * 8 + tig + 4]);
            pa[3] = __float_as_uint(Pst[(gid + 8) * LDK + kt * 8 + tig + 4]);
            #pragma unroll
            for (int nt = 0; nt < 8; nt++) {
                unsigned b0 = __float_as_uint(Vsh[(kt * 8 + tig    ) * LDK + nt * 8 + gid]);
                unsigned b1 = __float_as_uint(Vsh[(kt * 8 + tig + 4) * LDK + nt * 8 + gid]);
                mma_tf32(o[nt], pa, b0, b1);
            }
        }
    }

    // ---- epilogue: normalize and store ----
    const float inv0 = 1.0f / l0;
    const float inv1 = 1.0f / l1;
    float* obase = out + ((size_t)bh * S_LEN + q0) * DH;
    #pragma unroll
    for (int nt = 0; nt < 8; nt++) {
        const int c = nt * 8 + 2 * tig;
        float2 w0 = make_float2(o[nt][0] * inv0, o[nt][1] * inv0);
        float2 w1 = make_float2(o[nt][2] * inv1, o[nt][3] * inv1);
        *(float2*)(obase + (size_t)gid       * DH + c) = w0;
        *(float2*)(obase + (size_t)(gid + 8) * DH + c) = w1;
    }
}

extern "C" void kernel_launch(void* const* d_in, const int* in_sizes, int n_in,
                              void* d_out, int out_size)
{
    const float* Q    = (const float*)d_in[0];
    const float* K    = (const float*)d_in[1];
    const float* V    = (const float*)d_in[2];
    const float* mask = (const float*)d_in[3];
    float* out = (float*)d_out;

    dim3 grid(S_LEN / BM, 2 * HEADS);   // 32 x 32 blocks
    fa_tf32_kernel<<<grid, NTHREADS>>>(Q, K, V, mask, out);
}

// round 2
// speedup vs baseline: 1.0034x; 1.0034x over previous
#include <cuda_runtime.h>
#include <cstdint>

#define S_LEN   2048
#define HEADS   16
#define DH      64
#define BM      64
#define BN      64
#define LDK     68          // padded stride (floats) for shared tiles
#define NTHREADS 128

__device__ __forceinline__ unsigned f2tf32(float f) {
    unsigned r;
    asm("cvt.rna.tf32.f32 %0, %1;" : "=r"(r) : "f"(f));
    return r;
}

__device__ __forceinline__ void mma_tf32(float c[4], const unsigned a[4],
                                         unsigned b0, unsigned b1) {
    asm volatile(
        "mma.sync.aligned.m16n8k8.row.col.f32.tf32.tf32.f32 "
        "{%0,%1,%2,%3}, {%4,%5,%6,%7}, {%8,%9}, {%0,%1,%2,%3};\n"
        : "+f"(c[0]), "+f"(c[1]), "+f"(c[2]), "+f"(c[3])
        : "r"(a[0]), "r"(a[1]), "r"(a[2]), "r"(a[3]), "r"(b0), "r"(b1));
}

__global__ __launch_bounds__(NTHREADS, 4)
void fa_tf32_kernel(const float* __restrict__ Q, const float* __restrict__ K,
                    const float* __restrict__ V, const float* __restrict__ mask,
                    float* __restrict__ out)
{
    __shared__ float Ksh[BN * LDK];   // K tile; reused as P staging after QK^T
    __shared__ float Vsh[BN * LDK];
    __shared__ float msh[BN];

    const int tid  = threadIdx.x;
    const int warp = tid >> 5;
    const int lane = tid & 31;
    const int gid  = lane >> 2;   // row group 0..7
    const int tig  = lane & 3;    // thread-in-group 0..3

    const int bh = blockIdx.y;            // fused b*H + h
    const int b  = bh / HEADS;
    const int q0 = blockIdx.x * BM + warp * 16;

    const float* Qbase = Q + ((size_t)bh * S_LEN + q0) * DH;
    const float* Kbase = K + (size_t)bh * S_LEN * DH;
    const float* Vbase = V + (size_t)bh * S_LEN * DH;
    const float* mbase = mask + (size_t)b * S_LEN;

    // ---- Q fragments (tf32), pre-scaled by 1/sqrt(64) = 0.125 (exact) ----
    unsigned qa[8][4];
    #pragma unroll
    for (int kt = 0; kt < 8; kt++) {
        const int c0 = kt * 8 + tig;
        qa[kt][0] = f2tf32(Qbase[(size_t)gid       * DH + c0    ] * 0.125f);
        qa[kt][1] = f2tf32(Qbase[(size_t)(gid + 8) * DH + c0    ] * 0.125f);
        qa[kt][2] = f2tf32(Qbase[(size_t)gid       * DH + c0 + 4] * 0.125f);
        qa[kt][3] = f2tf32(Qbase[(size_t)(gid + 8) * DH + c0 + 4] * 0.125f);
    }

    float o[8][4];
    #pragma unroll
    for (int nt = 0; nt < 8; nt++)
        #pragma unroll
        for (int j = 0; j < 4; j++) o[nt][j] = 0.f;

    float m0 = -1e30f, m1 = -1e30f;   // running row maxima (rows gid, gid+8)
    float l0 = 0.f,   l1 = 0.f;       // running row sums

    for (int kv0 = 0; kv0 < S_LEN; kv0 += BN) {
        __syncthreads();   // prior iteration's PV reads of Ksh/Vsh complete

        // ---- cooperative load of K, V tiles (tf32-converted) + mask ----
        #pragma unroll
        for (int it = 0; it < 8; it++) {
            const int i  = tid + it * NTHREADS;      // 0..1023
            const int r  = i >> 4;
            const int c4 = (i & 15) << 2;
            const float4 k4 = *(const float4*)(Kbase + (size_t)(kv0 + r) * DH + c4);
            Ksh[r * LDK + c4 + 0] = __uint_as_float(f2tf32(k4.x));
            Ksh[r * LDK + c4 + 1] = __uint_as_float(f2tf32(k4.y));
            Ksh[r * LDK + c4 + 2] = __uint_as_float(f2tf32(k4.z));
            Ksh[r * LDK + c4 + 3] = __uint_as_float(f2tf32(k4.w));
            const float4 v4 = *(const float4*)(Vbase + (size_t)(kv0 + r) * DH + c4);
            Vsh[r * LDK + c4 + 0] = __uint_as_float(f2tf32(v4.x));
            Vsh[r * LDK + c4 + 1] = __uint_as_float(f2tf32(v4.y));
            Vsh[r * LDK + c4 + 2] = __uint_as_float(f2tf32(v4.z));
            Vsh[r * LDK + c4 + 3] = __uint_as_float(f2tf32(v4.w));
        }
        if (tid < BN) msh[tid] = -1000000.0f * (1.0f - mbase[kv0 + tid]);
        __syncthreads();

        // ---- S = Q K^T  (scaled already), 16x64 per warp ----
        float sacc[8][4];
        #pragma unroll
        for (int nt = 0; nt < 8; nt++) {
            #pragma unroll
            for (int j = 0; j < 4; j++) sacc[nt][j] = 0.f;
            #pragma unroll
            for (int kt = 0; kt < 8; kt++) {
                const float* kp = &Ksh[(nt * 8 + gid) * LDK + kt * 8 + tig];
                unsigned b0 = __float_as_uint(kp[0]);
                unsigned b1 = __float_as_uint(kp[4]);
                mma_tf32(sacc[nt], qa[kt], b0, b1);
            }
        }

        // ---- additive mask + online softmax ----
        float mx0 = -1e30f, mx1 = -1e30f;
        #pragma unroll
        for (int nt = 0; nt < 8; nt++) {
            const float add0 = msh[nt * 8 + 2 * tig];
            const float add1 = msh[nt * 8 + 2 * tig + 1];
            sacc[nt][0] += add0; sacc[nt][1] += add1;
            sacc[nt][2] += add0; sacc[nt][3] += add1;
            mx0 = fmaxf(mx0, fmaxf(sacc[nt][0], sacc[nt][1]));
            mx1 = fmaxf(mx1, fmaxf(sacc[nt][2], sacc[nt][3]));
        }
        mx0 = fmaxf(mx0, __shfl_xor_sync(0xffffffffu, mx0, 1));
        mx0 = fmaxf(mx0, __shfl_xor_sync(0xffffffffu, mx0, 2));
        mx1 = fmaxf(mx1, __shfl_xor_sync(0xffffffffu, mx1, 1));
        mx1 = fmaxf(mx1, __shfl_xor_sync(0xffffffffu, mx1, 2));

        const float nm0 = fmaxf(m0, mx0);
        const float nm1 = fmaxf(m1, mx1);
        const float al0 = __expf(m0 - nm0);
        const float al1 = __expf(m1 - nm1);

        float s0 = 0.f, s1 = 0.f;
        #pragma unroll
        for (int nt = 0; nt < 8; nt++) {
            float p0 = __expf(sacc[nt][0] - nm0);
            float p1 = __expf(sacc[nt][1] - nm0);
            float p2 = __expf(sacc[nt][2] - nm1);
            float p3 = __expf(sacc[nt][3] - nm1);
            s0 += p0 + p1;
            s1 += p2 + p3;
            sacc[nt][0] = p0; sacc[nt][1] = p1;
            sacc[nt][2] = p2; sacc[nt][3] = p3;
        }
        s0 += __shfl_xor_sync(0xffffffffu, s0, 1);
        s0 += __shfl_xor_sync(0xffffffffu, s0, 2);
        s1 += __shfl_xor_sync(0xffffffffu, s1, 1);
        s1 += __shfl_xor_sync(0xffffffffu, s1, 2);
        l0 = l0 * al0 + s0;
        l1 = l1 * al1 + s1;
        m0 = nm0; m1 = nm1;

        #pragma unroll
        for (int nt = 0; nt < 8; nt++) {
            o[nt][0] *= al0; o[nt][1] *= al0;
            o[nt][2] *= al1; o[nt][3] *= al1;
        }

        // ---- stage P (tf32) into this warp's 16 rows of Ksh (K is dead) ----
        __syncthreads();   // all warps finished reading K tile
        float* Pst = Ksh + warp * 16 * LDK;
        #pragma unroll
        for (int nt = 0; nt < 8; nt++) {
            const int c = nt * 8 + 2 * tig;
            Pst[gid * LDK + c    ]      = __uint_as_float(f2tf32(sacc[nt][0]));
            Pst[gid * LDK + c + 1]      = __uint_as_float(f2tf32(sacc[nt][1]));
            Pst[(gid + 8) * LDK + c    ] = __uint_as_float(f2tf32(sacc[nt][2]));
            Pst[(gid + 8) * LDK + c + 1] = __uint_as_float(f2tf32(sacc[nt][3]));
        }
        __syncwarp();

        // ---- O += P @ V ----
        #pragma unroll
        for (int kt = 0; kt < 8; kt++) {
            unsigned pa[4];
            pa[0] = __float_as_uint(Pst[gid       * LDK + kt * 8 + tig    ]);
            pa[1] = __float_as_uint(Pst[(gid + 8) * LDK + kt * 8 + tig    ]);
            pa[2] = __float_as_uint(Pst[gid       * LDK + kt * 8 + tig + 4]);
            pa[3] = __float_as_uint(Pst[(gid + 8) * LDK + kt * 8 + tig + 4]);
            #pragma unroll
            for (int nt = 0; nt < 8; nt++) {
                unsigned b0 = __float_as_uint(Vsh[(kt * 8 + tig    ) * LDK + nt * 8 + gid]);
                unsigned b1 = __float_as_uint(Vsh[(kt * 8 + tig + 4) * LDK + nt * 8 + gid]);
                mma_tf32(o[nt], pa, b0, b1);
            }
        }
    }

    // ---- epilogue: normalize and store ----
    const float inv0 = 1.0f / l0;
    const float inv1 = 1.0f / l1;
    float* obase = out + ((size_t)bh * S_LEN + q0) * DH;
    #pragma unroll
    for (int nt = 0; nt < 8; nt++) {
        const int c = nt * 8 + 2 * tig;
        float2 w0 = make_float2(o[nt][0] * inv0, o[nt][1] * inv0);
        float2 w1 = make_float2(o[nt][2] * inv1, o[nt][3] * inv1);
        *(float2*)(obase + (size_t)gid       * DH + c) = w0;
        *(float2*)(obase + (size_t)(gid + 8) * DH + c) = w1;
    }
}

extern "C" void kernel_launch(void* const* d_in, const int* in_sizes, int n_in,
                              void* d_out, int out_size)
{
    const float* Q    = (const float*)d_in[0];
    const float* K    = (const float*)d_in[1];
    const float* V    = (const float*)d_in[2];
    const float* mask = (const float*)d_in[3];
    float* out = (float*)d_out;

    dim3 grid(S_LEN / BM, 2 * HEADS);   // 32 x 32 blocks
    fa_tf32_kernel<<<grid, NTHREADS>>>(Q, K, V, mask, out);
}